// round 17
// baseline (speedup 1.0000x reference)
#include <cuda_runtime.h>
#include <cstdint>

// Problem constants (fixed by the dataset)
#define NJ     25
#define CIN    256
#define HID    128

#define APITCH 132               // A tile pitch (uint = bf16x2)
#define YPAD   132               // y pitch (float)

typedef unsigned long long ull;

__device__ __forceinline__ void fma2(ull& d, ull a, ull b) {
    asm("fma.rn.f32x2 %0, %1, %2, %0;" : "+l"(d) : "l"(a), "l"(b));
}
__device__ __forceinline__ float lo2(ull v){ return __uint_as_float((unsigned)v); }
__device__ __forceinline__ float hi2(ull v){ return __uint_as_float((unsigned)(v >> 32)); }
__device__ __forceinline__ unsigned pk_bf16x2(float even, float odd) {
    unsigned r;
    asm("cvt.rn.bf16x2.f32 %0, %1, %2;" : "=r"(r) : "f"(odd), "f"(even));
    return r;
}
// convert one float2 -> (hi bf16x2, lo bf16x2)
__device__ __forceinline__ void split2(float2 v, unsigned& hi, unsigned& lo) {
    hi = pk_bf16x2(v.x, v.y);
    const float fx = __uint_as_float(hi << 16);
    const float fy = __uint_as_float(hi & 0xFFFF0000u);
    lo = pk_bf16x2(v.x - fx, v.y - fy);
}
__device__ __forceinline__ void mma16816(float* d,
    unsigned a0, unsigned a1, unsigned a2, unsigned a3,
    unsigned b0, unsigned b1)
{
    asm volatile(
        "mma.sync.aligned.m16n8k16.row.col.f32.bf16.bf16.f32 "
        "{%0,%1,%2,%3},{%4,%5,%6,%7},{%8,%9},{%0,%1,%2,%3};"
        : "+f"(d[0]), "+f"(d[1]), "+f"(d[2]), "+f"(d[3])
        : "r"(a0), "r"(a1), "r"(a2), "r"(a3), "r"(b0), "r"(b1));
}

// ============================================================================
// Single fused per-batch kernel, pipeline-free GEMM.
//   A (src) converted to bf16 hi/lo smem tiles once; W1 fragments LDG'd
//   directly from gmem (L1/L2-hot, warp-local rows) and split in registers.
//   y = S @ W1^T via mma.sync (Sh*Wh + Sh*Wl + Sl*Wh, fp32 acc);
//   then z-reduction + R13-proven phase-3 epilogue.
// ============================================================================
__global__ __launch_bounds__(256, 2)
void fused_edge_kernel(const float* __restrict__ src,
                       const float* __restrict__ W1,
                       const float* __restrict__ alpha_p,
                       const float* __restrict__ W2,
                       float* __restrict__ out)
{
    __shared__ unsigned sAH[32 * APITCH];     // 16.9 KB  (rows 25-31 garbage)
    __shared__ unsigned sAL[32 * APITCH];     // 16.9 KB
    __shared__ float    sY[NJ * YPAD];        // 13.2 KB
    __shared__ float    sW2[HID];
    __shared__ float    sZ[NJ];

    const int tid  = threadIdx.x;
    const int b    = blockIdx.x;
    const int lane = tid & 31, warp = tid >> 5;
    const int ra   = lane >> 2;       // fragment row/col group
    const int q    = lane & 3;        // thread-in-group

    // ---- direct LDG -> bf16 hi/lo convert -> A tiles; W2 ----
    {
        const float* srcB = src + (size_t)b * NJ * CIN;
        #pragma unroll
        for (int k = 0; k < 7; k++) {
            const int idx = k * 256 + tid;
            if (idx < 1600) {
                const float4 v = *reinterpret_cast<const float4*>(srcB + idx * 4);
                const int r = idx >> 6, c4 = idx & 63;
                unsigned h0v, l0v, h1v, l1v;
                split2(make_float2(v.x, v.y), h0v, l0v);
                split2(make_float2(v.z, v.w), h1v, l1v);
                const int o = r * APITCH + c4 * 2;
                sAH[o] = h0v; sAH[o + 1] = h1v;
                sAL[o] = l0v; sAL[o + 1] = l1v;
            }
        }
        if (tid < HID) sW2[tid] = W2[tid];
    }
    __syncthreads();                  // A tiles ready

    // ---- phase 2: barrier-free split GEMM; W fragments straight from gmem ----
    float acc[2][2][4];
    #pragma unroll
    for (int mt = 0; mt < 2; mt++)
        #pragma unroll
        for (int nt = 0; nt < 2; nt++)
            #pragma unroll
            for (int e = 0; e < 4; e++) acc[mt][nt][e] = 0.0f;

    const int h0 = warp * 16 + ra;
    const float* w0p = W1 + (size_t)h0 * CIN + 2 * q;        // row h0
    const float* w1p = w0p + 8 * CIN;                        // row h0+8

    #pragma unroll
    for (int kc = 0; kc < 4; kc++) {
        const unsigned* aH = sAH + kc * 32;
        const unsigned* aL = sAL + kc * 32;
        #pragma unroll
        for (int ks = 0; ks < 4; ks++) {
            const int colb = kc * 64 + ks * 16;              // + 2q in pointer
            // B fragments: LDG + in-register split (each value used once)
            const float2 f00 = *reinterpret_cast<const float2*>(w0p + colb);
            const float2 f01 = *reinterpret_cast<const float2*>(w0p + colb + 8);
            const float2 f10 = *reinterpret_cast<const float2*>(w1p + colb);
            const float2 f11 = *reinterpret_cast<const float2*>(w1p + colb + 8);
            unsigned bH0, bL0, bH1, bL1, bH2, bL2, bH3, bL3;
            split2(f00, bH0, bL0);
            split2(f01, bH1, bL1);
            split2(f10, bH2, bL2);
            split2(f11, bH3, bL3);

            const int kp = ks * 8 + q;
            const unsigned aH0 = aH[(ra)      * APITCH + kp];
            const unsigned aH1 = aH[(ra + 8)  * APITCH + kp];
            const unsigned aH2 = aH[(ra)      * APITCH + kp + 4];
            const unsigned aH3 = aH[(ra + 8)  * APITCH + kp + 4];
            const unsigned aH4 = aH[(ra + 16) * APITCH + kp];
            const unsigned aH5 = aH[(ra + 24) * APITCH + kp];
            const unsigned aH6 = aH[(ra + 16) * APITCH + kp + 4];
            const unsigned aH7 = aH[(ra + 24) * APITCH + kp + 4];
            const unsigned aL0 = aL[(ra)      * APITCH + kp];
            const unsigned aL1 = aL[(ra + 8)  * APITCH + kp];
            const unsigned aL2 = aL[(ra)      * APITCH + kp + 4];
            const unsigned aL3 = aL[(ra + 8)  * APITCH + kp + 4];
            const unsigned aL4 = aL[(ra + 16) * APITCH + kp];
            const unsigned aL5 = aL[(ra + 24) * APITCH + kp];
            const unsigned aL6 = aL[(ra + 16) * APITCH + kp + 4];
            const unsigned aL7 = aL[(ra + 24) * APITCH + kp + 4];

            // Sh*Wh
            mma16816(acc[0][0], aH0, aH1, aH2, aH3, bH0, bH1);
            mma16816(acc[0][1], aH0, aH1, aH2, aH3, bH2, bH3);
            mma16816(acc[1][0], aH4, aH5, aH6, aH7, bH0, bH1);
            mma16816(acc[1][1], aH4, aH5, aH6, aH7, bH2, bH3);
            // Sh*Wl
            mma16816(acc[0][0], aH0, aH1, aH2, aH3, bL0, bL1);
            mma16816(acc[0][1], aH0, aH1, aH2, aH3, bL2, bL3);
            mma16816(acc[1][0], aH4, aH5, aH6, aH7, bL0, bL1);
            mma16816(acc[1][1], aH4, aH5, aH6, aH7, bL2, bL3);
            // Sl*Wh
            mma16816(acc[0][0], aL0, aL1, aL2, aL3, bH0, bH1);
            mma16816(acc[0][1], aL0, aL1, aL2, aL3, bH2, bH3);
            mma16816(acc[1][0], aL4, aL5, aL6, aL7, bH0, bH1);
            mma16816(acc[1][1], aL4, aL5, aL6, aL7, bH2, bH3);
        }
    }

    // ---- store y into sY ----
    #pragma unroll
    for (int mt = 0; mt < 2; mt++) {
        #pragma unroll
        for (int nt = 0; nt < 2; nt++) {
            const int col = warp * 16 + nt * 8 + 2 * q;
            const int r0 = mt * 16 + ra;
            if (r0 < NJ)
                *reinterpret_cast<float2*>(sY + r0 * YPAD + col) =
                    make_float2(acc[mt][nt][0], acc[mt][nt][1]);
            if (r0 + 8 < NJ)
                *reinterpret_cast<float2*>(sY + (r0 + 8) * YPAD + col) =
                    make_float2(acc[mt][nt][2], acc[mt][nt][3]);
        }
    }
    __syncthreads();

    // ---- z[n] = sum_h W2[h]*y[n][h] (warp per n) ----
    for (int n = warp; n < NJ; n += 8) {
        const float* yr = sY + n * YPAD;
        float v = sW2[lane]      * yr[lane]
                + sW2[lane + 32] * yr[lane + 32]
                + sW2[lane + 64] * yr[lane + 64]
                + sW2[lane + 96] * yr[lane + 96];
        #pragma unroll
        for (int o = 16; o > 0; o >>= 1)
            v += __shfl_xor_sync(0xffffffffu, v, o);
        if (lane == 0) sZ[n] = v;
    }
    __syncthreads();

    // ---- phase 3 (R13): j on lanes, i = warp + 8t; 8 indep chains/warp ----
    {
        const float alpha = alpha_p[0];
        const float c1 = 0.5f * (1.0f + alpha);
        const float c2 = 0.5f * (1.0f - alpha);
        const ull NEG1  = 0xBF800000BF800000ull;
        const ull AMASK = 0x7FFFFFFF7FFFFFFFull;

        ull accP[4] = {0ull, 0ull, 0ull, 0ull};
        ull accQ[4] = {0ull, 0ull, 0ull, 0ull};
        const int jr = (lane < NJ) ? lane : (NJ - 1);
        const float* yjrow = sY + jr * YPAD;

        #pragma unroll
        for (int hc = 0; hc < 8; hc++) {
            const int hb = hc * 16;
            const ulonglong2 yjA = *reinterpret_cast<const ulonglong2*>(yjrow + hb);
            const ulonglong2 yjB = *reinterpret_cast<const ulonglong2*>(yjrow + hb + 4);
            const ulonglong2 yjC = *reinterpret_cast<const ulonglong2*>(yjrow + hb + 8);
            const ulonglong2 yjD = *reinterpret_cast<const ulonglong2*>(yjrow + hb + 12);
            const ulonglong2 wA  = *reinterpret_cast<const ulonglong2*>(sW2 + hb);
            const ulonglong2 wB  = *reinterpret_cast<const ulonglong2*>(sW2 + hb + 4);
            const ulonglong2 wC  = *reinterpret_cast<const ulonglong2*>(sW2 + hb + 8);
            const ulonglong2 wD  = *reinterpret_cast<const ulonglong2*>(sW2 + hb + 12);

            #pragma unroll
            for (int t = 0; t < 4; t++) {
                const int i = warp + 8 * t;
                if (i < NJ) {
                    const float* yir = sY + i * YPAD + hb;
                    const ulonglong2 yiA = *reinterpret_cast<const ulonglong2*>(yir);
                    const ulonglong2 yiB = *reinterpret_cast<const ulonglong2*>(yir + 4);
                    const ulonglong2 yiC = *reinterpret_cast<const ulonglong2*>(yir + 8);
                    const ulonglong2 yiD = *reinterpret_cast<const ulonglong2*>(yir + 12);
                    ull d;
                    d = yjA.x; fma2(d, yiA.x, NEG1); d &= AMASK; fma2(accP[t], d, wA.x);
                    d = yjA.y; fma2(d, yiA.y, NEG1); d &= AMASK; fma2(accQ[t], d, wA.y);
                    d = yjB.x; fma2(d, yiB.x, NEG1); d &= AMASK; fma2(accP[t], d, wB.x);
                    d = yjB.y; fma2(d, yiB.y, NEG1); d &= AMASK; fma2(accQ[t], d, wB.y);
                    d = yjC.x; fma2(d, yiC.x, NEG1); d &= AMASK; fma2(accP[t], d, wC.x);
                    d = yjC.y; fma2(d, yiC.y, NEG1); d &= AMASK; fma2(accQ[t], d, wC.y);
                    d = yjD.x; fma2(d, yiD.x, NEG1); d &= AMASK; fma2(accP[t], d, wD.x);
                    d = yjD.y; fma2(d, yiD.y, NEG1); d &= AMASK; fma2(accQ[t], d, wD.y);
                }
            }
        }

        float* outB = out + (size_t)b * NJ * NJ;
        if (lane < NJ) {
            const float zj = sZ[lane];
            #pragma unroll
            for (int t = 0; t < 4; t++) {
                const int i = warp + 8 * t;
                if (i < NJ) {
                    const float S = lo2(accP[t]) + hi2(accP[t])
                                  + lo2(accQ[t]) + hi2(accQ[t]);
                    outB[i * NJ + lane] = c1 * (zj - sZ[i]) + c2 * S;
                }
            }
        }
    }
}

extern "C" void kernel_launch(void* const* d_in, const int* in_sizes, int n_in,
                              void* d_out, int out_size)
{
    // metadata order: src, heads, ends, pair_ids, W1, alpha, W2
    const float* src   = (const float*)d_in[0];
    const float* W1    = (const float*)d_in[4];
    const float* alpha = (const float*)d_in[5];
    const float* W2    = (const float*)d_in[6];
    float* out = (float*)d_out;

    const int batch = in_sizes[0] / (NJ * CIN);          // 256
    fused_edge_kernel<<<batch, 256>>>(src, W1, alpha, W2, out);
}